// round 6
// baseline (speedup 1.0000x reference)
#include <cuda_runtime.h>
#include <cstdint>

// PolicyEncoder gather-sum:
// out[n, :] = bias + w_state0[obs0[n]] + w_state1[obs1[n]] + w_act0[act0[n]] + w_act1[act1[n]]
// N = 262144 rows, D = 128 floats per row.
//
// R6: persistent warps + TWO interleaved software-pipelined row streams.
//  - grid = 148 SMs * 3 blocks * 8 warps = 3552 warps (single exact wave).
//  - Each warp owns two row streams: A = gw + k*2W, B = gw + W + k*2W.
//    Both are 2-stage pipelined: per iteration we prefetch next-pair indices,
//    issue next-pair gathers (8 loads), and consume the current pair whose
//    gathers were issued one iteration ago. Steady state: 8 gathers + 8 index
//    loads in flight per warp -> ~96KB of reads in flight per SM.
//  - Streaming stores (__stcs) keep the 134MB output out of L2.

struct Idx { int i0, i1, i2, i3; };

__device__ __forceinline__ Idx load_idx(const int* __restrict__ o0,
                                        const int* __restrict__ o1,
                                        const int* __restrict__ a0,
                                        const int* __restrict__ a1, int r) {
    Idx x;
    x.i0 = __ldg(o0 + r);
    x.i1 = __ldg(o1 + r);
    x.i2 = __ldg(a0 + r);
    x.i3 = __ldg(a1 + r);
    return x;
}

__global__ void __launch_bounds__(256, 3)
policy_encoder_kernel(const int* __restrict__ obs0,
                      const int* __restrict__ obs1,
                      const int* __restrict__ act0,
                      const int* __restrict__ act1,
                      const float4* __restrict__ w0,   // [OBS0, 32] as float4
                      const float4* __restrict__ w1,
                      const float4* __restrict__ w2,
                      const float4* __restrict__ w3,
                      const float4* __restrict__ bias, // [32]
                      float4* __restrict__ out,        // [N, 32]
                      int n)
{
    const int lane = threadIdx.x & 31;
    const int gw   = (int)((blockIdx.x * blockDim.x + threadIdx.x) >> 5);
    const int W    = (int)((gridDim.x * blockDim.x) >> 5);   // total warps
    const int last = n - 1;

    if (gw > last) return;

    const float4 b = __ldg(bias + lane);

    // ---- prologue: pair 0 indices + gathers, pair 1 indices ----
    Idx iA = load_idx(obs0, obs1, act0, act1, gw);
    {
        int rB = gw + W;
        Idx iB = load_idx(obs0, obs1, act0, act1, rB <= last ? rB : last);

        // keep iB alive via gathers below
        float4 gA0 = __ldg(w0 + (size_t)iA.i0 * 32 + lane);
        float4 gA1 = __ldg(w1 + (size_t)iA.i1 * 32 + lane);
        float4 gA2 = __ldg(w2 + (size_t)iA.i2 * 32 + lane);
        float4 gA3 = __ldg(w3 + (size_t)iA.i3 * 32 + lane);
        float4 gB0 = __ldg(w0 + (size_t)iB.i0 * 32 + lane);
        float4 gB1 = __ldg(w1 + (size_t)iB.i1 * 32 + lane);
        float4 gB2 = __ldg(w2 + (size_t)iB.i2 * 32 + lane);
        float4 gB3 = __ldg(w3 + (size_t)iB.i3 * 32 + lane);

        int rA1 = gw + 2 * W, rB1 = gw + 3 * W;
        Idx iAn = load_idx(obs0, obs1, act0, act1, rA1 <= last ? rA1 : last);
        Idx iBn = load_idx(obs0, obs1, act0, act1, rB1 <= last ? rB1 : last);

        // ---- steady state: consume pair k, gathers for pair k+1 in flight ----
        for (int r = gw; r <= last; r += 2 * W) {
            // indices for pair k+2
            int rAnn = r + 4 * W, rBnn = r + 5 * W;
            Idx iAnn = load_idx(obs0, obs1, act0, act1, rAnn <= last ? rAnn : last);
            Idx iBnn = load_idx(obs0, obs1, act0, act1, rBnn <= last ? rBnn : last);

            // gathers for pair k+1 (indices arrived last iteration)
            float4 hA0 = __ldg(w0 + (size_t)iAn.i0 * 32 + lane);
            float4 hA1 = __ldg(w1 + (size_t)iAn.i1 * 32 + lane);
            float4 hA2 = __ldg(w2 + (size_t)iAn.i2 * 32 + lane);
            float4 hA3 = __ldg(w3 + (size_t)iAn.i3 * 32 + lane);
            float4 hB0 = __ldg(w0 + (size_t)iBn.i0 * 32 + lane);
            float4 hB1 = __ldg(w1 + (size_t)iBn.i1 * 32 + lane);
            float4 hB2 = __ldg(w2 + (size_t)iBn.i2 * 32 + lane);
            float4 hB3 = __ldg(w3 + (size_t)iBn.i3 * 32 + lane);

            // consume pair k (gathers issued one iteration ago)
            float4 res;
            res.x = b.x + gA0.x + gA1.x + gA2.x + gA3.x;
            res.y = b.y + gA0.y + gA1.y + gA2.y + gA3.y;
            res.z = b.z + gA0.z + gA1.z + gA2.z + gA3.z;
            res.w = b.w + gA0.w + gA1.w + gA2.w + gA3.w;
            __stcs(out + (size_t)r * 32 + lane, res);

            int rB_cur = r + W;
            if (rB_cur <= last) {
                float4 resB;
                resB.x = b.x + gB0.x + gB1.x + gB2.x + gB3.x;
                resB.y = b.y + gB0.y + gB1.y + gB2.y + gB3.y;
                resB.z = b.z + gB0.z + gB1.z + gB2.z + gB3.z;
                resB.w = b.w + gB0.w + gB1.w + gB2.w + gB3.w;
                __stcs(out + (size_t)rB_cur * 32 + lane, resB);
            }

            // rotate pipeline registers
            gA0 = hA0; gA1 = hA1; gA2 = hA2; gA3 = hA3;
            gB0 = hB0; gB1 = hB1; gB2 = hB2; gB3 = hB3;
            iAn = iAnn; iBn = iBnn;
        }
    }
}

extern "C" void kernel_launch(void* const* d_in, const int* in_sizes, int n_in,
                              void* d_out, int out_size)
{
    const int*    obs0 = (const int*)d_in[0];
    const int*    obs1 = (const int*)d_in[1];
    const int*    act0 = (const int*)d_in[2];
    const int*    act1 = (const int*)d_in[3];
    const float4* w0   = (const float4*)d_in[4];
    const float4* w1   = (const float4*)d_in[5];
    const float4* w2   = (const float4*)d_in[6];
    const float4* w3   = (const float4*)d_in[7];
    const float4* bias = (const float4*)d_in[8];
    float4*       out  = (float4*)d_out;

    const int n = in_sizes[0];     // number of rows (N)
    const int threads = 256;       // 8 warps/block
    const int blocks  = 148 * 3;   // one exact wave at 3 blocks/SM

    policy_encoder_kernel<<<blocks, threads>>>(obs0, obs1, act0, act1,
                                               w0, w1, w2, w3, bias, out, n);
}